// round 1
// baseline (speedup 1.0000x reference)
#include <cuda_runtime.h>
#include <cstdint>

// Problem constants (fixed shapes: cls_scores (4,8,80,80), gt_boxes (4,64,5))
#define HH 80
#define WW 80
#define BATCH 4
#define KK 64
#define AA 4
#define NUNIQ (AA*HH*WW)          // 25600 unique anchors (per batch-replica)
#define NANCH (BATCH*NUNIQ)       // 102400 anchors in output
// Output layout (concatenated float32):
//   overlaps  [4][102400][64]   @ 0
//   max_ovl   [4][102400]       @ O_MAX
//   argmax    [4][102400]       @ O_ARG  (indices as float)
//   gt_max    [4][64]           @ O_GTM
#define O_MAX ((size_t)BATCH*NANCH*KK)          // 26214400
#define O_ARG (O_MAX + (size_t)BATCH*NANCH)     // 26624000
#define O_GTM (O_ARG + (size_t)BATCH*NANCH)     // 27033600

__global__ void init_gtmax_kernel(float* out) {
    // gt_max is reduced via atomicMax on int bits of non-negative floats;
    // init to +0.0f (int 0). Everything else is fully overwritten.
    int t = threadIdx.x;
    if (t < BATCH * KK) out[O_GTM + t] = 0.0f;
}

__global__ __launch_bounds__(256)
void anchor_overlaps_kernel(const float* __restrict__ gt, float* __restrict__ out)
{
    __shared__ float s_raw[KK * 5];     // gt boxes for this batch
    __shared__ float s_max[256];        // per-anchor max (block's 256 anchors)
    __shared__ float s_arg[256];        // per-anchor argmax (as float)
    __shared__ float s_gt[16 * 64];     // per-(arow, k) partial gt_max

    const int tid  = threadIdx.x;
    const int b    = blockIdx.y;        // batch
    const int kq   = tid & 15;          // k-quad: covers k = kq*4 .. kq*4+3
    const int arow = tid >> 4;          // anchor lane within iteration (0..15)
    const int base_n = blockIdx.x * 256; // this block covers unique anchors [base_n, base_n+256)

    // ---- Load gt boxes for batch b into SMEM ----
    for (int i = tid; i < KK * 5; i += 256) s_raw[i] = gt[b * KK * 5 + i];
    __syncthreads();

    // ---- Per-thread gt params for its 4 k's (fixed for the whole block) ----
    float G0[4], G1[4], G2P[4], G3P[4], GAREA[4], GTM[4];
    #pragma unroll
    for (int j = 0; j < 4; j++) {
        int k = kq * 4 + j;
        float g0 = s_raw[k*5+0], g1 = s_raw[k*5+1];
        float g2 = s_raw[k*5+2], g3 = s_raw[k*5+3];
        float gx = g2 - g0 + 1.0f;
        float gy = g3 - g1 + 1.0f;
        G0[j] = g0; G1[j] = g1;
        G2P[j] = g2 + 1.0f;             // min(a2,g2)+1 == min(a2+1, g2+1)
        G3P[j] = g3 + 1.0f;
        GAREA[j] = gx * gy;
        GTM[j] = (gx == 1.0f && gy == 1.0f) ? 0.0f : 1.0f;  // gt_zero -> overlap 0
    }

    float gmax[4] = {-1.0f, -1.0f, -1.0f, -1.0f};  // running gt_max partials
    float4* o4 = (float4*)out;
    const size_t rep4 = (size_t)NUNIQ * (KK / 4);  // replica stride in float4 units

    for (int it = 0; it < 16; it++) {
        int n   = base_n + it * 16 + arow;          // unique anchor index [0, 25600)
        int a   = n / (HH * WW);
        int rem = n - a * (HH * WW);
        int y   = rem / WW;
        int x   = rem - y * WW;

        // Anchor per reference: sizes = {2,4,8,16} -> half = 1<<a (exact)
        float s2 = (float)(1 << a);
        float fx = (float)x, fy = (float)y;
        float x0c = fminf(fmaxf(fx - s2, 0.0f), 79.0f);
        float x2c = fminf(fmaxf(fx + s2, 0.0f), 79.0f);
        float y0c = fminf(fmaxf(fy - s2, 0.0f), 79.0f);
        float y2c = fminf(fmaxf(fy + s2, 0.0f), 79.0f);
        // Stored anchor = [x0c, y0c, w, h]; reference IoU reads cols as [x1,y1,x2,y2]:
        float ax1 = x0c, aw = x2c - x0c;
        float ay1 = y0c, ah = y2c - y0c;
        float anx  = aw - ax1 + 1.0f;
        float any_ = ah - ay1 + 1.0f;
        bool  anzero = (anx == 1.0f) && (any_ == 1.0f);
        float anarea = anx * any_;
        float awp1 = aw + 1.0f, ahp1 = ah + 1.0f;

        float inter[4], ov[4];
        #pragma unroll
        for (int j = 0; j < 4; j++) {
            float iw = fmaxf(fminf(awp1, G2P[j]) - fmaxf(ax1, G0[j]), 0.0f);
            float ih = fmaxf(fminf(ahp1, G3P[j]) - fmaxf(ay1, G1[j]), 0.0f);
            inter[j] = iw * ih;
            ov[j] = 0.0f;                           // inter==0 -> 0/ua == 0 exactly
        }
        // ~98% of warps skip the MUFU divisions entirely (warp-uniform branch)
        bool need = (inter[0] > 0.0f) | (inter[1] > 0.0f) |
                    (inter[2] > 0.0f) | (inter[3] > 0.0f);
        if (__any_sync(0xffffffffu, need)) {
            #pragma unroll
            for (int j = 0; j < 4; j++) {
                if (inter[j] > 0.0f)
                    ov[j] = __fdividef(inter[j], anarea + GAREA[j] - inter[j]);
            }
        }
        #pragma unroll
        for (int j = 0; j < 4; j++) {
            ov[j] *= GTM[j];                        // gt_zero -> 0
            if (anzero) ov[j] = -1.0f;              // an_zero -> -1 (overrides)
            gmax[j] = fmaxf(gmax[j], ov[j]);
        }

        // ---- Store overlaps: 4 replicas, fully coalesced float4 ----
        float4 v = make_float4(ov[0], ov[1], ov[2], ov[3]);
        size_t idx4 = ((size_t)b * NANCH + n) * (KK / 4) + kq;
        o4[idx4]            = v;
        o4[idx4 + rep4]     = v;
        o4[idx4 + 2*rep4]   = v;
        o4[idx4 + 3*rep4]   = v;

        // ---- max/argmax over k for this anchor (first-index tie semantics) ----
        float bv = ov[0]; int bi = kq * 4;
        #pragma unroll
        for (int j = 1; j < 4; j++)
            if (ov[j] > bv) { bv = ov[j]; bi = kq * 4 + j; }
        #pragma unroll
        for (int m = 8; m >= 1; m >>= 1) {          // 16-lane groups (xor<16 keeps bit4)
            float o2 = __shfl_xor_sync(0xffffffffu, bv, m);
            int   i2 = __shfl_xor_sync(0xffffffffu, bi, m);
            if (o2 > bv || (o2 == bv && i2 < bi)) { bv = o2; bi = i2; }
        }
        if (kq == 0) {
            s_max[it * 16 + arow] = bv;
            s_arg[it * 16 + arow] = (float)bi;
        }
    }

    // ---- Stage gt_max partials ----
    #pragma unroll
    for (int j = 0; j < 4; j++) s_gt[arow * 64 + kq * 4 + j] = gmax[j];
    __syncthreads();

    // ---- Write max/argmax, 4 replicas, coalesced ----
    {
        float mv = s_max[tid], av = s_arg[tid];
        size_t mb = O_MAX + (size_t)b * NANCH + base_n + tid;
        size_t ab = O_ARG + (size_t)b * NANCH + base_n + tid;
        #pragma unroll
        for (int r = 0; r < 4; r++) {
            out[mb + (size_t)r * NUNIQ] = mv;
            out[ab + (size_t)r * NUNIQ] = av;
        }
    }

    // ---- gt_max: reduce 16 partials per k, one atomic per (block, k) ----
    if (tid < 64) {
        float v = s_gt[tid];
        #pragma unroll
        for (int g = 1; g < 16; g++) v = fmaxf(v, s_gt[g * 64 + tid]);
        v = fmaxf(v, 0.0f);  // true gt_max >= 0 always; keeps int-bit compare valid
        atomicMax((int*)(out + O_GTM + b * KK + tid), __float_as_int(v));
    }
}

extern "C" void kernel_launch(void* const* d_in, const int* in_sizes, int n_in,
                              void* d_out, int out_size)
{
    // gt_boxes has 4*64*5 = 1280 elements; cls_scores has 204800 (only shape matters).
    const float* gt = (const float*)d_in[0];
    for (int i = 0; i < n_in; i++) {
        if (in_sizes[i] == BATCH * KK * 5) { gt = (const float*)d_in[i]; break; }
    }
    float* out = (float*)d_out;

    init_gtmax_kernel<<<1, 256>>>(out);
    dim3 grid(NUNIQ / 256, BATCH);   // (100, 4)
    anchor_overlaps_kernel<<<grid, 256>>>(gt, out);
}

// round 2
// speedup vs baseline: 1.0145x; 1.0145x over previous
#include <cuda_runtime.h>
#include <cstdint>

// Fixed shapes: cls_scores (4,8,80,80), gt_boxes (4,64,5)
#define HH 80
#define WW 80
#define BATCH 4
#define KK 64
#define AA 4
#define PLANE (HH*WW)             // 6400 anchors per (a) plane
#define NUNIQ (AA*PLANE)          // 25600 unique anchors
#define NANCH (BATCH*NUNIQ)       // 102400 anchors in output
// Output layout (concatenated float32):
//   overlaps  [4][102400][64]   @ 0
//   max_ovl   [4][102400]       @ O_MAX
//   argmax    [4][102400]       @ O_ARG  (indices as float)
//   gt_max    [4][64]           @ O_GTM
#define O_MAX ((size_t)BATCH*NANCH*KK)          // 26214400
#define O_ARG (O_MAX + (size_t)BATCH*NANCH)     // 26624000
#define O_GTM (O_ARG + (size_t)BATCH*NANCH)     // 27033600

__global__ void init_gtmax_kernel(float* out) {
    int t = threadIdx.x;
    if (t < BATCH * KK) out[O_GTM + t] = 0.0f;  // int bits 0 for atomicMax
}

// Grid: (100 tiles, AA, BATCH). Block = 256 threads = 16 anchor-lanes x 16 k-quads.
// Each block covers 64 consecutive anchors within one (b, a) plane, 4 iterations.
__global__ __launch_bounds__(256)
void anchor_overlaps_kernel(const float* __restrict__ gt, float* __restrict__ out)
{
    __shared__ float s_raw[KK * 5];
    __shared__ float s_max[64];
    __shared__ float s_arg[64];
    __shared__ float s_gt[16 * 64];

    const int tid  = threadIdx.x;
    const int kq   = tid & 15;          // k-quad: k = kq*4 .. kq*4+3
    const int arow = tid >> 4;          // anchor lane (0..15)
    const int tile = blockIdx.x;        // 0..99
    const int a    = blockIdx.y;        // anchor size index
    const int b    = blockIdx.z;        // batch

    // gt boxes for this batch -> SMEM
    for (int i = tid; i < KK * 5; i += 256) s_raw[i] = gt[b * KK * 5 + i];
    __syncthreads();

    // Per-thread gt params for its 4 k's
    float G0[4], G1[4], G2P[4], G3P[4], GAREA[4];
    #pragma unroll
    for (int j = 0; j < 4; j++) {
        int k = kq * 4 + j;
        float g0 = s_raw[k*5+0], g1 = s_raw[k*5+1];
        float g2 = s_raw[k*5+2], g3 = s_raw[k*5+3];
        float gx = g2 - g0 + 1.0f;
        float gy = g3 - g1 + 1.0f;
        G0[j] = g0; G1[j] = g1;
        // gt_zero (gx==1 && gy==1) -> force iw<=0 -> ov==0 (matches reference mask)
        bool gz = (gx == 1.0f) && (gy == 1.0f);
        G2P[j] = gz ? -1e30f : g2 + 1.0f;   // min(a2,g2)+1 == min(a2+1,g2+1)
        G3P[j] = g3 + 1.0f;
        GAREA[j] = gx * gy;
    }

    // Anchor-size half-width is uniform per block
    const float s2 = (float)(1 << a);

    // Plane coords of this thread's first anchor; advances by +16 per iteration
    int p0 = tile * 64 + arow;          // < 6400
    int y  = p0 / WW;
    int x  = p0 - y * WW;

    float gmax[4] = {-1.0f, -1.0f, -1.0f, -1.0f};
    float4* o4 = (float4*)out;
    const unsigned rep4 = (unsigned)NUNIQ * (KK / 4);   // replica stride (float4)
    // overlaps index (float4 units) for iteration 0
    unsigned idx4 = ((unsigned)b * NANCH + (unsigned)a * PLANE + (unsigned)p0) * (KK/4) + kq;

    #pragma unroll
    for (int it = 0; it < 4; it++) {
        float fx = (float)x, fy = (float)y;
        // x in [0,79], s2>0  =>  fx-s2 <= 79 and fx+s2 >= 0 always
        float x0c = fmaxf(fx - s2, 0.0f);
        float x2c = fminf(fx + s2, 79.0f);
        float y0c = fmaxf(fy - s2, 0.0f);
        float y2c = fminf(fy + s2, 79.0f);
        // Stored anchor = [x0c, y0c, w, h]; reference IoU reads cols as [x1,y1,x2,y2]
        float ax1 = x0c, aw = x2c - x0c;
        float ay1 = y0c, ah = y2c - y0c;
        float anx  = aw - ax1 + 1.0f;
        float any_ = ah - ay1 + 1.0f;
        bool  anzero = (anx == 1.0f) && (any_ == 1.0f);
        float anarea = anx * any_;
        float awp1 = aw + 1.0f, ahp1 = ah + 1.0f;

        float inter[4], ov[4];
        #pragma unroll
        for (int j = 0; j < 4; j++) {
            float iw = fmaxf(fminf(awp1, G2P[j]) - fmaxf(ax1, G0[j]), 0.0f);
            float ih = fmaxf(fminf(ahp1, G3P[j]) - fmaxf(ay1, G1[j]), 0.0f);
            inter[j] = iw * ih;
            ov[j] = 0.0f;                       // inter==0 -> 0 exactly
        }
        bool need = (inter[0] > 0.0f) | (inter[1] > 0.0f) |
                    (inter[2] > 0.0f) | (inter[3] > 0.0f);
        if (__any_sync(0xffffffffu, need)) {    // ~98% of warps skip all RCPs
            #pragma unroll
            for (int j = 0; j < 4; j++) {
                if (inter[j] > 0.0f)
                    ov[j] = __fdividef(inter[j], anarea + GAREA[j] - inter[j]);
            }
        }
        #pragma unroll
        for (int j = 0; j < 4; j++) {
            if (anzero) ov[j] = -1.0f;          // an_zero -> -1 (overrides)
            gmax[j] = fmaxf(gmax[j], ov[j]);
        }

        // ---- overlaps: 4 replicas, coalesced float4 ----
        float4 v = make_float4(ov[0], ov[1], ov[2], ov[3]);
        o4[idx4]            = v;
        o4[idx4 + rep4]     = v;
        o4[idx4 + 2*rep4]   = v;
        o4[idx4 + 3*rep4]   = v;

        // ---- max/argmax over this anchor's 64 k's (first-index ties) ----
        float bv = ov[0]; int bi = kq * 4;
        #pragma unroll
        for (int j = 1; j < 4; j++)
            if (ov[j] > bv) { bv = ov[j]; bi = kq * 4 + j; }
        #pragma unroll
        for (int m = 8; m >= 1; m >>= 1) {      // reduce across the 16 kq lanes
            float o2 = __shfl_xor_sync(0xffffffffu, bv, m);
            int   i2 = __shfl_xor_sync(0xffffffffu, bi, m);
            if (o2 > bv || (o2 == bv && i2 < bi)) { bv = o2; bi = i2; }
        }
        if (kq == 0) {
            s_max[it * 16 + arow] = bv;
            s_arg[it * 16 + arow] = (float)bi;
        }

        // advance to next anchor: plane index += 16
        idx4 += 16 * (KK / 4);
        x += 16;
        if (x >= WW) { x -= WW; y += 1; }
    }

    // gt_max partials
    #pragma unroll
    for (int j = 0; j < 4; j++) s_gt[arow * 64 + kq * 4 + j] = gmax[j];
    __syncthreads();

    // ---- max/argmax out: 64 anchors, 4 replicas, coalesced ----
    if (tid < 64) {
        float mv = s_max[tid], av = s_arg[tid];
        size_t base = (size_t)b * NANCH + (size_t)a * PLANE + (size_t)tile * 64 + tid;
        #pragma unroll
        for (int r = 0; r < 4; r++) {
            out[O_MAX + base + (size_t)r * NUNIQ] = mv;
            out[O_ARG + base + (size_t)r * NUNIQ] = av;
        }
        // ---- gt_max: reduce 16 partials for k=tid, one atomic ----
        float vgt = s_gt[tid];
        #pragma unroll
        for (int g = 1; g < 16; g++) vgt = fmaxf(vgt, s_gt[g * 64 + tid]);
        vgt = fmaxf(vgt, 0.0f);   // true gt_max >= 0; int-bit compare stays valid
        atomicMax((int*)(out + O_GTM + b * KK + tid), __float_as_int(vgt));
    }
}

extern "C" void kernel_launch(void* const* d_in, const int* in_sizes, int n_in,
                              void* d_out, int out_size)
{
    const float* gt = (const float*)d_in[0];
    for (int i = 0; i < n_in; i++) {
        if (in_sizes[i] == BATCH * KK * 5) { gt = (const float*)d_in[i]; break; }
    }
    float* out = (float*)d_out;

    init_gtmax_kernel<<<1, 256>>>(out);
    dim3 grid(PLANE / 64, AA, BATCH);   // (100, 4, 4) = 1600 blocks
    anchor_overlaps_kernel<<<grid, 256>>>(gt, out);
}